// round 3
// baseline (speedup 1.0000x reference)
#include <cuda_runtime.h>
#include <cstdint>

// ---------------------------------------------------------------------------
// Direct circular-convolution Net_CCL, round 3: column-packed f32x2.
//
//   x      : [16,2,64,256] -> [32,64,256] (c_in = 1)
//   L1: conv w1[50,1,3,7]  + b1, maxpool(2,4), relu   -> buf1 [32,50,32,64]
//   L2: conv w2[50,50,3,7] + b2, maxpool(2,4), relu   -> buf2 [32,50,16,16]
//   merge: out[b] = s[2b] + mean(s[2b+1])             -> bufM [16,50,16,16]
//   L3: upsample(2,4) conv w3[50,50,3,5] + b3, relu   -> buf3 [16,50,32,64]
//   L4: upsample(2,4) conv w4[50,50,3,7] + b4, relu   -> buf4 [16,50,64,256]
//   L5: conv w5[1,50,3,7]  + b5, sigmoid              -> out  [16,64,256]
//
// f2 lanes hold ADJACENT OUTPUT COLUMNS; weights are lane-duplicated (w,w).
// Dense layers: per-thread 8-float register window -> even-q operand pairs
// come straight from aligned LDS.64; only odd-q pairs need a repack.
// Upsampled layers: 4 output cols sharing one input col grouped per thread.
// ---------------------------------------------------------------------------

typedef unsigned long long f2;

__device__ __forceinline__ void fma2(f2 &a, f2 v, f2 w) {
    asm("fma.rn.f32x2 %0, %1, %2, %0;" : "+l"(a) : "l"(v), "l"(w));
}
__device__ __forceinline__ f2 pack2(float lo, float hi) {
    f2 r; asm("mov.b64 %0, {%1, %2};" : "=l"(r) : "f"(lo), "f"(hi)); return r;
}
__device__ __forceinline__ float2 unpack2(f2 a) {
    float2 r; asm("mov.b64 {%0, %1}, %2;" : "=f"(r.x), "=f"(r.y) : "l"(a)); return r;
}
__device__ __forceinline__ f2 dup2(float v) { return pack2(v, v); }
__device__ __forceinline__ f2 ld_f2(const float* p) {
    return *reinterpret_cast<const f2*>(p);
}

__device__ float g_buf1[32 * 50 * 32 * 64];    // 13.1 MB
__device__ float g_buf2[32 * 50 * 16 * 16];    //  1.6 MB
__device__ float g_bufM[16 * 50 * 16 * 16];    //  0.8 MB
__device__ float g_buf3[16 * 50 * 32 * 64];    //  6.6 MB
__device__ float g_buf4[16 * 50 * 64 * 256];   // 52.4 MB

// ------------------------- K1: conv1 + pool + relu -------------------------
// grid (4 rowchunks, 50 co, 32 b), block 128: thread jp owns cols 2jp,2jp+1.
__global__ __launch_bounds__(128) void k1_conv_pool(const float* __restrict__ x,
                                                    const float* __restrict__ w1,
                                                    const float* __restrict__ b1) {
    const int k0 = blockIdx.x * 16;
    const int co = blockIdx.y;
    const int b  = blockIdx.z;
    const int jp = threadIdx.x;
    const int c  = 2 * jp;

    __shared__ float sm[18][264];   // sm[e][i] = x[(k0-2+e)&63][(i-8)&255]
    __shared__ f2 wds[21];

    const float* img = x + (size_t)b * 16384;
    for (int i = threadIdx.x; i < 1152; i += 128) {
        int e = i >> 6, c4 = i & 63;
        int r = (k0 - 2 + e) & 63;
        *reinterpret_cast<float4*>(&sm[e][8 + 4 * c4]) =
            reinterpret_cast<const float4*>(img + r * 256)[c4];
    }
    if (threadIdx.x < 144) {
        int e = threadIdx.x >> 3, d = threadIdx.x & 7;
        int r = (k0 - 2 + e) & 63;
        sm[e][d] = img[r * 256 + 248 + d];
    }
    if (threadIdx.x < 21) wds[threadIdx.x] = dup2(w1[co * 21 + threadIdx.x]);
    __syncthreads();

    f2 wr[21];
#pragma unroll
    for (int k = 0; k < 21; k++) wr[k] = wds[k];

    f2 acc[16];
#pragma unroll
    for (int i = 0; i < 16; i++) acc[i] = 0ull;

#pragma unroll
    for (int e = 0; e < 18; e++) {
        const float* row = &sm[e][c + 2];
        f2 P0 = ld_f2(row), P1 = ld_f2(row + 2), P2 = ld_f2(row + 4), P3 = ld_f2(row + 6);
        float2 u0 = unpack2(P0), u1 = unpack2(P1), u2 = unpack2(P2), u3 = unpack2(P3);
        f2 O5 = pack2(u0.y, u1.x), O3 = pack2(u1.y, u2.x), O1 = pack2(u2.y, u3.x);
#pragma unroll
        for (int p = 0; p < 3; p++) {
            int il = e - 2 + p;
            if (il < 0 || il >= 16) continue;
            fma2(acc[il], P3, wr[7 * p + 0]);
            fma2(acc[il], O1, wr[7 * p + 1]);
            fma2(acc[il], P2, wr[7 * p + 2]);
            fma2(acc[il], O3, wr[7 * p + 3]);
            fma2(acc[il], P1, wr[7 * p + 4]);
            fma2(acc[il], O5, wr[7 * p + 5]);
            fma2(acc[il], P0, wr[7 * p + 6]);
        }
    }

    const float bias = b1[co];
    float* out = g_buf1 + ((size_t)(b * 50 + co) * 32 + (k0 >> 1)) * 64;
#pragma unroll
    for (int pr = 0; pr < 8; pr++) {
        float2 u = unpack2(acc[2 * pr]);
        float2 v = unpack2(acc[2 * pr + 1]);
        float m = fmaxf(fmaxf(u.x, u.y), fmaxf(v.x, v.y));
        m = fmaxf(m, __shfl_xor_sync(0xffffffffu, m, 1));
        if ((jp & 1) == 0) out[pr * 64 + (jp >> 1)] = fmaxf(m + bias, 0.f);
    }
}

// ------------------------- K2: conv2 + pool + relu -------------------------
// grid (13 co-quads, 32 b), block 256: j=t&31 colpair, h=(t>>5)&1 rowhalf,
// g=t>>6 co within quad. 16-row f2 accumulators, 18-row input window.
__global__ __launch_bounds__(256) void k2_conv_pool(const float* __restrict__ w2,
                                                    const float* __restrict__ b2) {
    const int b = blockIdx.y;
    const int t = threadIdx.x;
    const int j = t & 31;
    const int h = (t >> 5) & 1;
    const int g = t >> 6;
    const int co = blockIdx.x * 4 + g;
    const bool valid = (co < 50);
    const int cw = valid ? co : 49;
    const int c = 2 * j;

    __shared__ float sm[32][72];       // sm[r][i] = in[r][(i-8)&63]
    __shared__ f2 wds[4][1050];        // lane-duplicated weights per local co

    for (int i = t; i < 4200; i += 256) {
        int gg = i / 1050, k = i - gg * 1050;
        int c2 = blockIdx.x * 4 + gg; if (c2 > 49) c2 = 49;
        wds[gg][k] = dup2(w2[c2 * 1050 + k]);
    }

    f2 acc[16];
#pragma unroll
    for (int r = 0; r < 16; r++) acc[r] = 0ull;

    const int ebase = 16 * h - 2;      // first input row for this half
    const float* base = g_buf1 + (size_t)b * 50 * 2048;

    for (int ci = 0; ci < 50; ci++) {
        __syncthreads();
        {
            const float4* s4 = reinterpret_cast<const float4*>(base + ci * 2048);
#pragma unroll
            for (int u = 0; u < 2; u++) {
                int i = t + u * 256;          // i < 512
                int r = i >> 4, c4 = i & 15;
                *reinterpret_cast<float4*>(&sm[r][8 + 4 * c4]) = s4[i];
            }
            int r = t >> 3, d = t & 7;        // 256 pad elements
            sm[r][d] = base[ci * 2048 + r * 64 + 56 + d];
        }
        __syncthreads();

        f2 wr[21];
#pragma unroll
        for (int k = 0; k < 21; k++) wr[k] = wds[g][ci * 21 + k];

#pragma unroll
        for (int eu = 0; eu < 18; eu++) {
            int er = (ebase + eu) & 31;
            const float* row = &sm[er][c + 2];
            f2 P0 = ld_f2(row), P1 = ld_f2(row + 2), P2 = ld_f2(row + 4), P3 = ld_f2(row + 6);
            float2 u0 = unpack2(P0), u1 = unpack2(P1), u2 = unpack2(P2), u3 = unpack2(P3);
            f2 O5 = pack2(u0.y, u1.x), O3 = pack2(u1.y, u2.x), O1 = pack2(u2.y, u3.x);
#pragma unroll
            for (int p = 0; p < 3; p++) {
                int il = eu - 2 + p;
                if (il < 0 || il >= 16) continue;
                fma2(acc[il], P3, wr[7 * p + 0]);
                fma2(acc[il], O1, wr[7 * p + 1]);
                fma2(acc[il], P2, wr[7 * p + 2]);
                fma2(acc[il], O3, wr[7 * p + 3]);
                fma2(acc[il], P1, wr[7 * p + 4]);
                fma2(acc[il], O5, wr[7 * p + 5]);
                fma2(acc[il], P0, wr[7 * p + 6]);
            }
        }
    }

    const float bias = b2[cw];
    float* out = g_buf2 + (size_t)(b * 50 + cw) * 256;
#pragma unroll
    for (int pr = 0; pr < 8; pr++) {
        float2 u = unpack2(acc[2 * pr]);
        float2 v = unpack2(acc[2 * pr + 1]);
        float m = fmaxf(fmaxf(u.x, u.y), fmaxf(v.x, v.y));
        m = fmaxf(m, __shfl_xor_sync(0xffffffffu, m, 1));
        if (valid && (j & 1) == 0)
            out[(8 * h + pr) * 16 + (j >> 1)] = fmaxf(m + bias, 0.f);
    }
}

// ---------------- merge: out[b] = s[2b] + mean(s[2b+1]) --------------------
__global__ void k_merge() {
    const int co = blockIdx.x;
    const int b  = blockIdx.y;
    const int t  = threadIdx.x;

    const float* s0 = g_buf2 + (size_t)((2 * b) * 50 + co) * 256;
    const float* s1 = g_buf2 + (size_t)((2 * b + 1) * 50 + co) * 256;

    float v0 = s0[t];
    float v1 = s1[t];

    __shared__ float red[8];
    float s = v1;
#pragma unroll
    for (int o = 16; o; o >>= 1) s += __shfl_xor_sync(0xffffffffu, s, o);
    if ((t & 31) == 0) red[t >> 5] = s;
    __syncthreads();
    if (t < 32) {
        float ss = (t < 8) ? red[t] : 0.f;
#pragma unroll
        for (int o = 4; o; o >>= 1) ss += __shfl_xor_sync(0xffffffffu, ss, o);
        if (t == 0) red[0] = ss;
    }
    __syncthreads();
    const float mean = red[0] * (1.f / 256.f);

    g_bufM[(size_t)(b * 50 + co) * 256 + t] = v0 + mean;
}

// ---------------- K3: zero-upsample(2,4) + conv3(3x5) + relu ---------------
// Whole 50x16x16 image in smem, shared by a co-QUAD. Output cols grouped by
// input col: thread owns cols 4c1..4c1+3 (two f2 accs) x 8 rows.
// grid (13 co-quads, 16 b), block 256: c1=t&15, rc=(t>>4)&3, g=t>>6.
__global__ __launch_bounds__(256) void k3_upconv(const float* __restrict__ w3,
                                                 const float* __restrict__ b3) {
    const int b  = blockIdx.y;
    const int t  = threadIdx.x;
    const int c1 = t & 15;
    const int rc = (t >> 4) & 3;
    const int g  = t >> 6;
    const int co = blockIdx.x * 4 + g;
    const bool valid = (co < 50);

    extern __shared__ float dyn[];
    float* s  = dyn;                                  // [50][256]
    f2*    wq = reinterpret_cast<f2*>(dyn + 12800);   // [4][50][9]

    const float* src = g_bufM + (size_t)b * 50 * 256;
    {
        const float4* s4 = reinterpret_cast<const float4*>(src);
        float4* d4 = reinterpret_cast<float4*>(s);
        for (int i = t; i < 3200; i += 256) d4[i] = s4[i];
    }
    // weight pairs per (gg,ci,p): [3p+0]=(w0,w1) [3p+1]=(w2,w3) [3p+2]=(w4,0)
    for (int i = t; i < 1800; i += 256) {
        int gg = i / 450, r = i - gg * 450;
        int ci = r / 9, srem = r - ci * 9;
        int p = srem / 3, m = srem - p * 3;
        int c2 = blockIdx.x * 4 + gg; if (c2 > 49) c2 = 49;
        const float* wb = w3 + c2 * 750 + ci * 15 + p * 5;
        f2 v = (m == 0) ? pack2(wb[0], wb[1])
             : (m == 1) ? pack2(wb[2], wb[3])
                        : pack2(wb[4], 0.f);
        wq[(gg * 50 + ci) * 9 + srem] = v;
    }
    __syncthreads();

    const int c1m = (c1 - 1) & 15;
    f2 accA[8], accB[8];
#pragma unroll
    for (int k = 0; k < 8; k++) { accA[k] = 0ull; accB[k] = 0ull; }

    for (int ci = 0; ci < 50; ci++) {
        const float* sp = s + ci * 256;
        const f2* wv = wq + ((size_t)g * 50 + ci) * 9;
        f2 w0 = wv[0], w1 = wv[1], w2r = wv[2];
        f2 w3r = wv[3], w4r = wv[4], w5r = wv[5];
        f2 w6r = wv[6], w7r = wv[7], w8r = wv[8];
#pragma unroll
        for (int u = 0; u < 5; u++) {
            int m = (4 * rc - 1 + u) & 15;
            f2 d1 = dup2(sp[m * 16 + c1]);
            f2 d2 = dup2(sp[m * 16 + c1m]);
#pragma unroll
            for (int p = 0; p < 3; p++) {
                int k = 2 * u - 2 + p;
                if (k < 0 || k >= 8) continue;
                f2 wa = (p == 0) ? w0 : (p == 1) ? w3r : w6r;
                f2 wb = (p == 0) ? w1 : (p == 1) ? w4r : w7r;
                f2 wc = (p == 0) ? w2r : (p == 1) ? w5r : w8r;
                fma2(accA[k], d1, wa);
                fma2(accB[k], d1, wb);
                fma2(accA[k], d2, wc);
            }
        }
    }

    if (valid) {
        const float bias = b3[co];
        float* out = g_buf3 + ((size_t)(b * 50 + co) * 32 + 8 * rc) * 64 + 4 * c1;
#pragma unroll
        for (int k = 0; k < 8; k++) {
            float2 a = unpack2(accA[k]);
            float2 cc = unpack2(accB[k]);
            float4 o;
            o.x = fmaxf(a.x + bias, 0.f);
            o.y = fmaxf(a.y + bias, 0.f);
            o.z = fmaxf(cc.x + bias, 0.f);
            o.w = fmaxf(cc.y + bias, 0.f);
            *reinterpret_cast<float4*>(out + k * 64) = o;
        }
    }
}

// ---------------- K4: zero-upsample(2,4) + conv4(3x7) + relu ---------------
// Output cols grouped by input col: thread owns cols 4c1..4c1+3 (2 f2 accs)
// x 8 rows. grid (2 rowhalves, 50 co, 16 b), block 256: c1=t&63, rc=t>>6.
__global__ __launch_bounds__(256) void k4_upconv(const float* __restrict__ w4,
                                                 const float* __restrict__ b4) {
    const int half = blockIdx.x;
    const int co   = blockIdx.y;
    const int b    = blockIdx.z;
    const int t    = threadIdx.x;
    const int c1   = t & 63;
    const int rc   = t >> 6;
    const int c1m  = (c1 - 1) & 63;

    __shared__ float sm[17][64];
    __shared__ f2 wp[50][12];
    // wp[ci][4p+s]: s0=(w0,w1) s1=(w2,w3) s2=(w4,w5) s3=(w6,0)

    for (int i = t; i < 600; i += 256) {
        int ci = i / 12, r = i - ci * 12;
        int p = r >> 2, srem = r & 3;
        const float* wb = w4 + co * 1050 + ci * 21 + p * 7;
        wp[ci][r] = (srem < 3) ? pack2(wb[2 * srem], wb[2 * srem + 1])
                               : pack2(wb[6], 0.f);
    }

    f2 accA[8], accB[8];
#pragma unroll
    for (int k = 0; k < 8; k++) { accA[k] = 0ull; accB[k] = 0ull; }

    const int mb = 16 * half - 1;     // first input row staged
    const float* src = g_buf3 + (size_t)b * 50 * 2048;

    for (int ci = 0; ci < 50; ci++) {
        __syncthreads();
        for (int i = t; i < 272; i += 256) {
            int e = i >> 4, c4 = i & 15;
            int mm = (mb + e) & 31;
            *reinterpret_cast<float4*>(&sm[e][4 * c4]) =
                reinterpret_cast<const float4*>(src + ci * 2048 + mm * 64)[c4];
        }
        __syncthreads();

        f2 wv[12];
#pragma unroll
        for (int k = 0; k < 12; k++) wv[k] = wp[ci][k];

#pragma unroll
        for (int u = 0; u < 5; u++) {
            int e = 4 * rc + u;
            f2 d1 = dup2(sm[e][c1]);
            f2 d2 = dup2(sm[e][c1m]);
#pragma unroll
            for (int p = 0; p < 3; p++) {
                int k = 2 * u - 2 + p;
                if (k < 0 || k >= 8) continue;
                fma2(accA[k], d1, wv[4 * p + 0]);
                fma2(accB[k], d1, wv[4 * p + 1]);
                fma2(accA[k], d2, wv[4 * p + 2]);
                fma2(accB[k], d2, wv[4 * p + 3]);
            }
        }
    }

    const float bias = b4[co];
    const int R0 = 32 * half + 8 * rc;
    float* out = g_buf4 + ((size_t)(b * 50 + co) * 64 + R0) * 256 + 4 * c1;
#pragma unroll
    for (int k = 0; k < 8; k++) {
        float2 a = unpack2(accA[k]);
        float2 cc = unpack2(accB[k]);
        float4 o;
        o.x = fmaxf(a.x + bias, 0.f);
        o.y = fmaxf(a.y + bias, 0.f);
        o.z = fmaxf(cc.x + bias, 0.f);
        o.w = fmaxf(cc.y + bias, 0.f);
        *reinterpret_cast<float4*>(out + k * 256) = o;
    }
}

// ---------------------- K5: conv5 (50 -> 1) + sigmoid ----------------------
// Column-pair f2 accs, 4 output rows per block, register prefetch of next ci.
// grid (16 rowchunks, 16 b), block 128: thread jp owns cols 2jp, 2jp+1.
__global__ __launch_bounds__(128) void k5_conv_sig(const float* __restrict__ w5,
                                                   const float* __restrict__ b5,
                                                   float* __restrict__ out) {
    const int k0 = blockIdx.x * 4;
    const int b  = blockIdx.y;
    const int t  = threadIdx.x;
    const int c  = 2 * t;

    __shared__ float sm[6][264];
    __shared__ f2 wds[1050];

    for (int i = t; i < 1050; i += 128) wds[i] = dup2(w5[i]);

    const float* src = g_buf4 + (size_t)b * 50 * 16384;
    const int pe = t >> 3, pd = t & 7;                 // pad indices (t<48)
    const int prow = (k0 - 2 + pe) & 63;

    float4 st[3];
    float pads;
    auto load_ci = [&](int ci) {
#pragma unroll
        for (int u = 0; u < 3; u++) {
            int i = t + u * 128;
            int e = i >> 6, c4 = i & 63;
            int r = (k0 - 2 + e) & 63;
            st[u] = reinterpret_cast<const float4*>(src + (size_t)ci * 16384 + r * 256)[c4];
        }
        if (t < 48) pads = src[(size_t)ci * 16384 + prow * 256 + 248 + pd];
    };
    load_ci(0);

    f2 acc[4] = {0ull, 0ull, 0ull, 0ull};

    for (int ci = 0; ci < 50; ci++) {
        __syncthreads();
#pragma unroll
        for (int u = 0; u < 3; u++) {
            int i = t + u * 128;
            int e = i >> 6, c4 = i & 63;
            *reinterpret_cast<float4*>(&sm[e][8 + 4 * c4]) = st[u];
        }
        if (t < 48) sm[pe][pd] = pads;
        __syncthreads();
        if (ci + 1 < 50) load_ci(ci + 1);

        f2 wr[21];
#pragma unroll
        for (int k = 0; k < 21; k++) wr[k] = wds[ci * 21 + k];

#pragma unroll
        for (int e = 0; e < 6; e++) {
            const float* row = &sm[e][c + 2];
            f2 P0 = ld_f2(row), P1 = ld_f2(row + 2), P2 = ld_f2(row + 4), P3 = ld_f2(row + 6);
            float2 u0 = unpack2(P0), u1 = unpack2(P1), u2 = unpack2(P2), u3 = unpack2(P3);
            f2 O5 = pack2(u0.y, u1.x), O3 = pack2(u1.y, u2.x), O1 = pack2(u2.y, u3.x);
#pragma unroll
            for (int p = 0; p < 3; p++) {
                int il = e - 2 + p;
                if (il < 0 || il >= 4) continue;
                fma2(acc[il], P3, wr[7 * p + 0]);
                fma2(acc[il], O1, wr[7 * p + 1]);
                fma2(acc[il], P2, wr[7 * p + 2]);
                fma2(acc[il], O3, wr[7 * p + 3]);
                fma2(acc[il], P1, wr[7 * p + 4]);
                fma2(acc[il], O5, wr[7 * p + 5]);
                fma2(acc[il], P0, wr[7 * p + 6]);
            }
        }
    }

    const float bias = b5[0];
#pragma unroll
    for (int k = 0; k < 4; k++) {
        float2 a = unpack2(acc[k]);
        float2 o;
        o.x = 1.f / (1.f + __expf(-(a.x + bias)));
        o.y = 1.f / (1.f + __expf(-(a.y + bias)));
        *reinterpret_cast<float2*>(out + (size_t)(b * 64 + k0 + k) * 256 + c) = o;
    }
}

// ---------------------------------------------------------------------------
extern "C" void kernel_launch(void* const* d_in, const int* in_sizes, int n_in,
                              void* d_out, int out_size) {
    (void)in_sizes; (void)n_in; (void)out_size;
    const float* x  = (const float*)d_in[0];
    const float* w1 = (const float*)d_in[1];
    const float* b1 = (const float*)d_in[2];
    const float* w2 = (const float*)d_in[3];
    const float* b2 = (const float*)d_in[4];
    const float* w3 = (const float*)d_in[5];
    const float* b3 = (const float*)d_in[6];
    const float* w4 = (const float*)d_in[7];
    const float* b4 = (const float*)d_in[8];
    const float* w5 = (const float*)d_in[9];
    const float* b5 = (const float*)d_in[10];
    float* out = (float*)d_out;

    const int k3_smem = 12800 * 4 + 1800 * 8;   // 65600 B
    cudaFuncSetAttribute(k3_upconv,
                         cudaFuncAttributeMaxDynamicSharedMemorySize, k3_smem);

    k1_conv_pool<<<dim3(4, 50, 32), 128>>>(x, w1, b1);
    k2_conv_pool<<<dim3(13, 32), 256>>>(w2, b2);
    k_merge<<<dim3(50, 16), 256>>>();
    k3_upconv<<<dim3(13, 16), 256, k3_smem>>>(w3, b3);
    k4_upconv<<<dim3(2, 50, 16), 256>>>(w4, b4);
    k5_conv_sig<<<dim3(16, 16), 128>>>(w5, b5, out);
}